// round 7
// baseline (speedup 1.0000x reference)
#include <cuda_runtime.h>
#include <cuda_fp16.h>
#include <cstdint>
#include <cstddef>

#define DINL __device__ __forceinline__

// ---------------------------------------------------------------------------
// Scratch (device globals; no allocation allowed)
// ---------------------------------------------------------------------------
__device__ float g_wprojT[1024u * 1024u];
__device__ float g_bcomb[1024];
__device__ float g_h2[32u * 1024u * 1024u];     // [B*T, H] fp32 (134 MB)
__device__ float g_pooled[32 * 1024];
__device__ __align__(16) __half g_xhi[32u * 1024u * 1024u];
__device__ __align__(16) __half g_xlo[32u * 1024u * 1024u];
__device__ __align__(16) __half g_whi[1024u * 1024u];
__device__ __align__(16) __half g_wlo[1024u * 1024u];
__device__ __align__(16) __half g_ahi[1024u * 1024u];   // W_hid split
__device__ __align__(16) __half g_alo[1024u * 1024u];
__device__ __align__(16) __half g_bthi[1024u * 1024u];  // W_projT split
__device__ __align__(16) __half g_btlo[1024u * 1024u];

// Residual scale: lo' = (x - hi) * 2^12, combined as acc1 + acc2 * 2^-12.
static constexpr float LO_SCALE = 4096.0f;
static constexpr float LO_INV   = 1.0f / 4096.0f;

// ---------------------------------------------------------------------------
// PTX helpers (baseline compute_103-safe: cp.async, ldmatrix, mma.sync)
// ---------------------------------------------------------------------------
DINL uint32_t smem_u32(const void* p) {
    uint32_t r;
    asm("{ .reg .u64 t; cvta.to.shared.u64 t, %1; cvt.u32.u64 %0, t; }"
        : "=r"(r) : "l"(p));
    return r;
}
DINL void cp16(uint32_t dst, const void* src) {
    asm volatile("cp.async.cg.shared.global [%0], [%1], 16;"
                 :: "r"(dst), "l"(src) : "memory");
}
DINL void cp_commit() { asm volatile("cp.async.commit_group;" ::: "memory"); }
template <int N> DINL void cp_wait() {
    asm volatile("cp.async.wait_group %0;" :: "n"(N) : "memory");
}
DINL void ldsm_x4(uint32_t* r, uint32_t addr) {
    asm volatile("ldmatrix.sync.aligned.m8n8.x4.shared.b16 {%0,%1,%2,%3}, [%4];"
                 : "=r"(r[0]), "=r"(r[1]), "=r"(r[2]), "=r"(r[3]) : "r"(addr));
}
DINL void mma_f16(float* d, const uint32_t* a, const uint32_t* b) {
    asm volatile(
        "mma.sync.aligned.m16n8k16.row.col.f32.f16.f16.f32 "
        "{%0,%1,%2,%3}, {%4,%5,%6,%7}, {%8,%9}, {%0,%1,%2,%3};"
        : "+f"(d[0]), "+f"(d[1]), "+f"(d[2]), "+f"(d[3])
        : "r"(a[0]), "r"(a[1]), "r"(a[2]), "r"(a[3]), "r"(b[0]), "r"(b[1]));
}

// ---------------------------------------------------------------------------
// Block reduction helper (256 threads)
// ---------------------------------------------------------------------------
DINL float block_reduce_sum(float v) {
    __shared__ float sh[8];
    int lane = threadIdx.x & 31;
    int w = threadIdx.x >> 5;
    #pragma unroll
    for (int o = 16; o > 0; o >>= 1) v += __shfl_down_sync(0xFFFFFFFFu, v, o);
    if (lane == 0) sh[w] = v;
    __syncthreads();
    if (w == 0) {
        v = (lane < 8) ? sh[lane] : 0.0f;
        #pragma unroll
        for (int o = 4; o > 0; o >>= 1) v += __shfl_down_sync(0xFFFFFFFFu, v, o);
    }
    return v;
}

// ---------------------------------------------------------------------------
// Prep kernel: blocks [0,1024) transpose W_proj -> W_projT (32x32 tiles);
// blocks [1024,2048) compute b_comb[g] = W_hid[g,:]@b_proj + b_hid[g].
// ---------------------------------------------------------------------------
__global__ __launch_bounds__(256)
void prep_kernel(const float* __restrict__ W_proj,
                 const float* __restrict__ W_hid,
                 const float* __restrict__ b_proj,
                 const float* __restrict__ b_hid,
                 float* __restrict__ wprojT,
                 float* __restrict__ bcomb)
{
    if (blockIdx.x < 1024) {
        __shared__ float tile[32][33];
        int bx = blockIdx.x & 31, by = blockIdx.x >> 5;
        int tx = threadIdx.x & 31, ty = threadIdx.x >> 5;  // ty 0..7
        int x = bx * 32 + tx;
        #pragma unroll
        for (int j = 0; j < 32; j += 8)
            tile[ty + j][tx] = W_proj[(size_t)(by * 32 + ty + j) * 1024 + x];
        __syncthreads();
        x = by * 32 + tx;
        #pragma unroll
        for (int j = 0; j < 32; j += 8)
            wprojT[(size_t)(bx * 32 + ty + j) * 1024 + x] = tile[tx][ty + j];
    } else {
        int g = blockIdx.x - 1024;
        float s = 0.0f;
        for (int h = threadIdx.x; h < 1024; h += 256)
            s = fmaf(W_hid[g * 1024 + h], b_proj[h], s);
        s = block_reduce_sum(s);
        if (threadIdx.x == 0) bcomb[g] = s + b_hid[g];
    }
}

// ---------------------------------------------------------------------------
// fp32 -> (fp16 hi, fp16 lo*4096) split, vectorized.
// ---------------------------------------------------------------------------
__global__ __launch_bounds__(256)
void split_kernel(const float* __restrict__ src,
                  __half* __restrict__ hi, __half* __restrict__ lo, int n4)
{
    int i = blockIdx.x * 256 + threadIdx.x;
    if (i >= n4) return;
    float4 v = reinterpret_cast<const float4*>(src)[i];
    float f[4] = {v.x, v.y, v.z, v.w};
    uint32_t hw[2], lw[2];
    #pragma unroll
    for (int j = 0; j < 2; j++) {
        __half h0 = __float2half_rn(f[2 * j + 0]);
        __half h1 = __float2half_rn(f[2 * j + 1]);
        __half l0 = __float2half_rn((f[2 * j + 0] - __half2float(h0)) * LO_SCALE);
        __half l1 = __float2half_rn((f[2 * j + 1] - __half2float(h1)) * LO_SCALE);
        unsigned short uh0 = *reinterpret_cast<unsigned short*>(&h0);
        unsigned short uh1 = *reinterpret_cast<unsigned short*>(&h1);
        unsigned short ul0 = *reinterpret_cast<unsigned short*>(&l0);
        unsigned short ul1 = *reinterpret_cast<unsigned short*>(&l1);
        hw[j] = (uint32_t)uh0 | ((uint32_t)uh1 << 16);
        lw[j] = (uint32_t)ul0 | ((uint32_t)ul1 << 16);
    }
    reinterpret_cast<uint2*>(hi)[i] = make_uint2(hw[0], hw[1]);
    reinterpret_cast<uint2*>(lo)[i] = make_uint2(lw[0], lw[1]);
}

// ---------------------------------------------------------------------------
// Split-precision GEMM: C[m,n] = sum_k A[m,k]*B[n,k]
// hi*hi -> acc1 ; (lo'*hi + hi*lo') -> acc2 ; C = acc1 + acc2/4096.
// Tile 128x128, BK=64, 8 warps (2x4, warp tile 64x32), 3-stage cp.async,
// distance-1 fragment software pipeline. K fixed at 1024.
// Grid: (N/128, M/128).
// ---------------------------------------------------------------------------
static constexpr uint32_t AHI_OFF = 0u;
static constexpr uint32_t ALO_OFF = 16384u;
static constexpr uint32_t BHI_OFF = 32768u;
static constexpr uint32_t BLO_OFF = 49152u;
static constexpr uint32_t STAGE   = 65536u;
static constexpr int NCH = 16;                 // K=1024 / 64

__global__ __launch_bounds__(256, 1)
void hmma_gemm(const __half* __restrict__ Ahi, const __half* __restrict__ Alo,
               const __half* __restrict__ Bhi, const __half* __restrict__ Blo,
               const float* __restrict__ bias, float* __restrict__ fout,
               __half* __restrict__ hi_out, __half* __restrict__ lo_out)
{
    extern __shared__ __align__(1024) char smem[];
    const uint32_t sbase = smem_u32(smem);
    const int tid = threadIdx.x;
    const int wid = tid >> 5;
    const int lane = tid & 31;
    const int wm = (wid >> 2) * 64;       // 2 warp rows
    const int wn = (wid & 3) * 32;        // 4 warp cols
    const int m0 = blockIdx.y << 7;       // BM = 128
    const int n0 = blockIdx.x << 7;       // BN = 128

    float acc1[4][4][4], acc2[4][4][4];
    #pragma unroll
    for (int i = 0; i < 4; i++)
        #pragma unroll
        for (int j = 0; j < 4; j++)
            #pragma unroll
            for (int r = 0; r < 4; r++) { acc1[i][j][r] = 0.0f; acc2[i][j][r] = 0.0f; }

    auto load_stage = [&](int c, int s) {
        const uint32_t st = sbase + (uint32_t)s * STAGE;
        const int k0 = c << 6;
        #pragma unroll
        for (int it = 0; it < 4; it++) {          // 128 rows x 8 chunks
            int idx = it * 256 + tid;
            int row = idx >> 3, ch = idx & 7;
            uint32_t off = (uint32_t)(row * 128) +
                           (uint32_t)(((ch ^ (row & 7)) << 4));
            size_t ga = (size_t)(m0 + row) * 1024 + k0 + ch * 8;
            size_t gb = (size_t)(n0 + row) * 1024 + k0 + ch * 8;
            cp16(st + AHI_OFF + off, Ahi + ga);
            cp16(st + ALO_OFF + off, Alo + ga);
            cp16(st + BHI_OFF + off, Bhi + gb);
            cp16(st + BLO_OFF + off, Blo + gb);
        }
        cp_commit();
    };

    // Fragment ping-pong buffers (distance-1 software pipeline)
    uint32_t ah[2][4][4], al[2][4][4], bh[2][4][2], bl[2][4][2];

    auto load_frags = [&](int ks, uint32_t st, int buf) {
        #pragma unroll
        for (int i = 0; i < 4; i++) {
            int row = wm + i * 16 + (lane & 15);
            int ch = 2 * ks + (lane >> 4);
            uint32_t off = (uint32_t)(row * 128) +
                           (uint32_t)(((ch ^ (row & 7)) << 4));
            ldsm_x4(ah[buf][i], st + AHI_OFF + off);
            ldsm_x4(al[buf][i], st + ALO_OFF + off);
        }
        #pragma unroll
        for (int jj = 0; jj < 2; jj++) {
            int row = wn + jj * 16 + ((lane >> 4) << 3) + (lane & 7);
            int ch = 2 * ks + ((lane >> 3) & 1);
            uint32_t off = (uint32_t)(row * 128) +
                           (uint32_t)(((ch ^ (row & 7)) << 4));
            uint32_t t[4];
            ldsm_x4(t, st + BHI_OFF + off);
            bh[buf][2 * jj][0] = t[0]; bh[buf][2 * jj][1] = t[1];
            bh[buf][2 * jj + 1][0] = t[2]; bh[buf][2 * jj + 1][1] = t[3];
            ldsm_x4(t, st + BLO_OFF + off);
            bl[buf][2 * jj][0] = t[0]; bl[buf][2 * jj][1] = t[1];
            bl[buf][2 * jj + 1][0] = t[2]; bl[buf][2 * jj + 1][1] = t[3];
        }
    };

    load_stage(0, 0);
    load_stage(1, 1);

    #pragma unroll 1
    for (int c = 0; c < NCH; c++) {
        if (c >= NCH - 2) cp_wait<0>(); else cp_wait<1>();
        __syncthreads();
        if (c + 2 < NCH) load_stage(c + 2, (c + 2) % 3);

        const uint32_t st = sbase + (uint32_t)(c % 3) * STAGE;
        load_frags(0, st, 0);
        #pragma unroll
        for (int ks = 0; ks < 4; ks++) {
            const int cur = ks & 1;
            if (ks < 3) load_frags(ks + 1, st, cur ^ 1);
            // Three j-sweeps: spreads the acc2 dependency chains apart and
            // gives the prefetch LDSMs a long shadow of independent MMAs.
            #pragma unroll
            for (int i = 0; i < 4; i++)
                #pragma unroll
                for (int j = 0; j < 4; j++)
                    mma_f16(acc2[i][j], al[cur][i], bh[cur][j]);
            #pragma unroll
            for (int i = 0; i < 4; i++)
                #pragma unroll
                for (int j = 0; j < 4; j++)
                    mma_f16(acc1[i][j], ah[cur][i], bh[cur][j]);
            #pragma unroll
            for (int i = 0; i < 4; i++)
                #pragma unroll
                for (int j = 0; j < 4; j++)
                    mma_f16(acc2[i][j], ah[cur][i], bl[cur][j]);
        }
    }
    __syncthreads();

    // Epilogue: combine -> padded smem [128][132] -> global
    float* stg = reinterpret_cast<float*>(smem);
    #pragma unroll
    for (int i = 0; i < 4; i++) {
        int row = wm + i * 16 + (lane >> 2);
        #pragma unroll
        for (int j = 0; j < 4; j++) {
            int col = wn + j * 8 + (lane & 3) * 2;
            stg[row * 132 + col]           = fmaf(acc2[i][j][0], LO_INV, acc1[i][j][0]);
            stg[row * 132 + col + 1]       = fmaf(acc2[i][j][1], LO_INV, acc1[i][j][1]);
            stg[(row + 8) * 132 + col]     = fmaf(acc2[i][j][2], LO_INV, acc1[i][j][2]);
            stg[(row + 8) * 132 + col + 1] = fmaf(acc2[i][j][3], LO_INV, acc1[i][j][3]);
        }
    }
    __syncthreads();

    if (hi_out == nullptr) {
        #pragma unroll
        for (int it = 0; it < 16; it++) {
            int idx = it * 256 + tid;        // 4096 float4 slots
            int r = idx >> 5;
            int c4 = (idx & 31) << 2;
            float4 v = *reinterpret_cast<const float4*>(&stg[r * 132 + c4]);
            if (bias != nullptr) {
                const float4 b = *reinterpret_cast<const float4*>(&bias[n0 + c4]);
                v.x += b.x; v.y += b.y; v.z += b.z; v.w += b.w;
            }
            *reinterpret_cast<float4*>(&fout[(size_t)(m0 + r) * 1024 + n0 + c4]) = v;
        }
    } else {
        #pragma unroll
        for (int it = 0; it < 16; it++) {
            int idx = it * 256 + tid;
            int r = idx >> 5;
            int c4 = (idx & 31) << 2;
            float4 v = *reinterpret_cast<const float4*>(&stg[r * 132 + c4]);
            float f[4] = {v.x, v.y, v.z, v.w};
            uint32_t hw[2], lw[2];
            #pragma unroll
            for (int j = 0; j < 2; j++) {
                __half h0 = __float2half_rn(f[2 * j + 0]);
                __half h1 = __float2half_rn(f[2 * j + 1]);
                __half l0 = __float2half_rn((f[2 * j + 0] - __half2float(h0)) * LO_SCALE);
                __half l1 = __float2half_rn((f[2 * j + 1] - __half2float(h1)) * LO_SCALE);
                unsigned short uh0 = *reinterpret_cast<unsigned short*>(&h0);
                unsigned short uh1 = *reinterpret_cast<unsigned short*>(&h1);
                unsigned short ul0 = *reinterpret_cast<unsigned short*>(&l0);
                unsigned short ul1 = *reinterpret_cast<unsigned short*>(&l1);
                hw[j] = (uint32_t)uh0 | ((uint32_t)uh1 << 16);
                lw[j] = (uint32_t)ul0 | ((uint32_t)ul1 << 16);
            }
            size_t go = ((size_t)(m0 + r) * 1024 + n0 + c4) >> 2;  // uint2 index
            reinterpret_cast<uint2*>(hi_out)[go] = make_uint2(hw[0], hw[1]);
            reinterpret_cast<uint2*>(lo_out)[go] = make_uint2(lw[0], lw[1]);
        }
    }
}

// ---------------------------------------------------------------------------
// LIF scan over T (soft reset) + time-mean pooling. float4 per thread,
// 16-deep prefetch; 128 blocks x 64 threads.
// ---------------------------------------------------------------------------
__global__ __launch_bounds__(64)
void lif_kernel(const float* __restrict__ h2, float* __restrict__ pooled)
{
    int idx = blockIdx.x * 64 + threadIdx.x;   // 0..8191
    int b = idx >> 8;
    int g4 = idx & 255;
    const float4* p = reinterpret_cast<const float4*>(h2 + ((size_t)b << 20)) + g4;

    float v[4] = {0, 0, 0, 0}, acc[4] = {0, 0, 0, 0};
    for (int t0 = 0; t0 < 1024; t0 += 16) {
        float4 xv[16];
        #pragma unroll
        for (int i = 0; i < 16; i++)
            xv[i] = __ldg(p + (size_t)(t0 + i) * 256);
        #pragma unroll
        for (int i = 0; i < 16; i++) {
            float xs[4] = {xv[i].x, xv[i].y, xv[i].z, xv[i].w};
            #pragma unroll
            for (int c = 0; c < 4; c++) {
                v[c] = __fadd_rn(v[c], __fmul_rn(__fsub_rn(xs[c], v[c]), 0.5f));
                if (v[c] >= 1.0f) { acc[c] += 1.0f; v[c] = __fsub_rn(v[c], 1.0f); }
            }
        }
    }
    float4 r;
    r.x = acc[0] * (1.0f / 1024.0f); r.y = acc[1] * (1.0f / 1024.0f);
    r.z = acc[2] * (1.0f / 1024.0f); r.w = acc[3] * (1.0f / 1024.0f);
    reinterpret_cast<float4*>(pooled)[idx] = r;
}

// ---------------------------------------------------------------------------
// out[b,o] = sum_g pooled[b,g] * W_out[o,g] + b_out[o]
// ---------------------------------------------------------------------------
__global__ __launch_bounds__(256)
void head_kernel(const float* __restrict__ pooled,
                 const float* __restrict__ W_out,
                 const float* __restrict__ b_out,
                 float* __restrict__ out)
{
    int b = blockIdx.x / 10;
    int o = blockIdx.x % 10;
    float s = 0.0f;
    for (int g = threadIdx.x; g < 1024; g += 256)
        s = fmaf(pooled[b * 1024 + g], W_out[o * 1024 + g], s);
    s = block_reduce_sum(s);
    if (threadIdx.x == 0) out[blockIdx.x] = s + b_out[o];
}

// ---------------------------------------------------------------------------
extern "C" void kernel_launch(void* const* d_in, const int* in_sizes, int n_in,
                              void* d_out, int out_size)
{
    (void)in_sizes; (void)n_in; (void)out_size;
    const float* x      = (const float*)d_in[0];
    const float* W_proj = (const float*)d_in[1];
    const float* b_proj = (const float*)d_in[2];
    const float* W_hid  = (const float*)d_in[3];
    const float* b_hid  = (const float*)d_in[4];
    const float* W_out  = (const float*)d_in[5];
    const float* b_out  = (const float*)d_in[6];
    float* out = (float*)d_out;

    float *wprojT, *bcomb, *h2, *pooled;
    __half *xhi, *xlo, *whi, *wlo, *ahi, *alo, *bthi, *btlo;
    cudaGetSymbolAddress((void**)&wprojT, g_wprojT);
    cudaGetSymbolAddress((void**)&bcomb,  g_bcomb);
    cudaGetSymbolAddress((void**)&h2,     g_h2);
    cudaGetSymbolAddress((void**)&pooled, g_pooled);
    cudaGetSymbolAddress((void**)&xhi,    g_xhi);
    cudaGetSymbolAddress((void**)&xlo,    g_xlo);
    cudaGetSymbolAddress((void**)&whi,    g_whi);
    cudaGetSymbolAddress((void**)&wlo,    g_wlo);
    cudaGetSymbolAddress((void**)&ahi,    g_ahi);
    cudaGetSymbolAddress((void**)&alo,    g_alo);
    cudaGetSymbolAddress((void**)&bthi,   g_bthi);
    cudaGetSymbolAddress((void**)&btlo,   g_btlo);

    cudaFuncSetAttribute(hmma_gemm, cudaFuncAttributeMaxDynamicSharedMemorySize,
                         3 * (int)STAGE);

    // 0) x -> (xhi, xlo)
    split_kernel<<<32768, 256>>>(x, xhi, xlo, 32 * 1024 * 1024 / 4);
    // 1) W_projT = W_proj^T ; b_comb
    prep_kernel<<<2048, 256>>>(W_proj, W_hid, b_proj, b_hid, wprojT, bcomb);
    // 2,3) splits of W_hid and W_projT
    split_kernel<<<1024, 256>>>(W_hid,  ahi,  alo,  1024 * 1024 / 4);
    split_kernel<<<1024, 256>>>(wprojT, bthi, btlo, 1024 * 1024 / 4);
    // 4) W_comb = W_hid @ W_projT^T, split-written to (whi, wlo)
    hmma_gemm<<<dim3(8, 8), 256, 3 * STAGE>>>(
        ahi, alo, bthi, btlo, nullptr, nullptr, whi, wlo);
    // 5) h2 = x @ W_comb^T + b_comb
    hmma_gemm<<<dim3(8, 256), 256, 3 * STAGE>>>(
        xhi, xlo, whi, wlo, bcomb, h2, nullptr, nullptr);
    // 6) LIF + pool
    lif_kernel<<<128, 64>>>(h2, pooled);
    // 7) head
    head_kernel<<<320, 256>>>(pooled, W_out, b_out, out);
}

// round 8
// speedup vs baseline: 1.0834x; 1.0834x over previous
#include <cuda_runtime.h>
#include <cuda_fp16.h>
#include <cstdint>
#include <cstddef>

#define DINL __device__ __forceinline__

// ---------------------------------------------------------------------------
// Scratch (device globals; no allocation allowed)
// Packed layout for all fp16 GEMM operands: 16 KB tiles of (128 rows x 64 k),
// row-major over (rowtile, ktile), interior pre-swizzled for ldmatrix.
// ---------------------------------------------------------------------------
__device__ float g_wprojT[1024u * 1024u];
__device__ float g_bcomb[1024];
__device__ float g_h2[32u * 1024u * 1024u];     // [B*T, H] fp32 (134 MB)
__device__ float g_pooled[32 * 1024];
__device__ __align__(128) __half g_xhi[32u * 1024u * 1024u];
__device__ __align__(128) __half g_xlo[32u * 1024u * 1024u];
__device__ __align__(128) __half g_whi[1024u * 1024u];
__device__ __align__(128) __half g_wlo[1024u * 1024u];
__device__ __align__(128) __half g_ahi[1024u * 1024u];   // W_hid split
__device__ __align__(128) __half g_alo[1024u * 1024u];
__device__ __align__(128) __half g_bthi[1024u * 1024u];  // W_projT split
__device__ __align__(128) __half g_btlo[1024u * 1024u];

// Residual scale: lo' = (x - hi) * 2^12, combined as acc1 + acc2 * 2^-12.
static constexpr float LO_SCALE = 4096.0f;
static constexpr float LO_INV   = 1.0f / 4096.0f;

// ---------------------------------------------------------------------------
// PTX helpers (compute_103 baseline-safe)
// ---------------------------------------------------------------------------
DINL uint32_t smem_u32(const void* p) {
    uint32_t r;
    asm("{ .reg .u64 t; cvta.to.shared.u64 t, %1; cvt.u32.u64 %0, t; }"
        : "=r"(r) : "l"(p));
    return r;
}
DINL void ldsm_x4(uint32_t* r, uint32_t addr) {
    asm volatile("ldmatrix.sync.aligned.m8n8.x4.shared.b16 {%0,%1,%2,%3}, [%4];"
                 : "=r"(r[0]), "=r"(r[1]), "=r"(r[2]), "=r"(r[3]) : "r"(addr));
}
DINL void mma_f16(float* d, const uint32_t* a, const uint32_t* b) {
    asm volatile(
        "mma.sync.aligned.m16n8k16.row.col.f32.f16.f16.f32 "
        "{%0,%1,%2,%3}, {%4,%5,%6,%7}, {%8,%9}, {%0,%1,%2,%3};"
        : "+f"(d[0]), "+f"(d[1]), "+f"(d[2]), "+f"(d[3])
        : "r"(a[0]), "r"(a[1]), "r"(a[2]), "r"(a[3]), "r"(b[0]), "r"(b[1]));
}
DINL void mbar_init(uint32_t addr, uint32_t cnt) {
    asm volatile("mbarrier.init.shared.b64 [%0], %1;" :: "r"(addr), "r"(cnt) : "memory");
}
DINL void mbar_expect_tx(uint32_t addr, uint32_t bytes) {
    asm volatile("mbarrier.arrive.expect_tx.shared.b64 _, [%0], %1;"
                 :: "r"(addr), "r"(bytes) : "memory");
}
DINL void mbar_wait(uint32_t addr, uint32_t parity) {
    asm volatile(
        "{\n\t.reg .pred P;\n"
        "W1_%=:\n\tmbarrier.try_wait.parity.acquire.cta.shared::cta.b64 P, [%0], %1, 0x989680;\n\t"
        "@P bra W2_%=;\n\tbra W1_%=;\nW2_%=:\n\t}"
        :: "r"(addr), "r"(parity) : "memory");
}
// 1D bulk async copy global->smem, completion via mbarrier complete_tx.
DINL void bulk_g2s(uint32_t dst, const void* src, uint32_t bytes, uint32_t bar) {
    asm volatile(
        "cp.async.bulk.shared::cluster.global.mbarrier::complete_tx::bytes "
        "[%0], [%1], %2, [%3];"
        :: "r"(dst), "l"(src), "r"(bytes), "r"(bar) : "memory");
}

// Packed-tile byte offset of the 16B group holding (row, k..k+7).
DINL uint32_t pack_off16(uint32_t row, uint32_t k) {
    uint32_t tile  = (row >> 7) * 16u + (k >> 6);
    uint32_t local = (row & 127u) * 128u + ((k >> 3) & 7u) * 16u;
    local ^= (local >> 3) & 0x70u;           // SW128 swizzle
    return tile * 16384u + local;
}

// ---------------------------------------------------------------------------
// Block reduction helper (256 threads)
// ---------------------------------------------------------------------------
DINL float block_reduce_sum(float v) {
    __shared__ float sh[8];
    int lane = threadIdx.x & 31;
    int w = threadIdx.x >> 5;
    #pragma unroll
    for (int o = 16; o > 0; o >>= 1) v += __shfl_down_sync(0xFFFFFFFFu, v, o);
    if (lane == 0) sh[w] = v;
    __syncthreads();
    if (w == 0) {
        v = (lane < 8) ? sh[lane] : 0.0f;
        #pragma unroll
        for (int o = 4; o > 0; o >>= 1) v += __shfl_down_sync(0xFFFFFFFFu, v, o);
    }
    return v;
}

// ---------------------------------------------------------------------------
// Prep kernel: blocks [0,1024) transpose W_proj -> W_projT (32x32 tiles);
// blocks [1024,2048) compute b_comb[g] = W_hid[g,:]@b_proj + b_hid[g].
// ---------------------------------------------------------------------------
__global__ __launch_bounds__(256)
void prep_kernel(const float* __restrict__ W_proj,
                 const float* __restrict__ W_hid,
                 const float* __restrict__ b_proj,
                 const float* __restrict__ b_hid,
                 float* __restrict__ wprojT,
                 float* __restrict__ bcomb)
{
    if (blockIdx.x < 1024) {
        __shared__ float tile[32][33];
        int bx = blockIdx.x & 31, by = blockIdx.x >> 5;
        int tx = threadIdx.x & 31, ty = threadIdx.x >> 5;  // ty 0..7
        int x = bx * 32 + tx;
        #pragma unroll
        for (int j = 0; j < 32; j += 8)
            tile[ty + j][tx] = W_proj[(size_t)(by * 32 + ty + j) * 1024 + x];
        __syncthreads();
        x = by * 32 + tx;
        #pragma unroll
        for (int j = 0; j < 32; j += 8)
            wprojT[(size_t)(bx * 32 + ty + j) * 1024 + x] = tile[tx][ty + j];
    } else {
        int g = blockIdx.x - 1024;
        float s = 0.0f;
        for (int h = threadIdx.x; h < 1024; h += 256)
            s = fmaf(W_hid[g * 1024 + h], b_proj[h], s);
        s = block_reduce_sum(s);
        if (threadIdx.x == 0) bcomb[g] = s + b_hid[g];
    }
}

// ---------------------------------------------------------------------------
// fp32 row-major -> packed-swizzled-tile (fp16 hi, fp16 lo*4096).
// One thread per 8-element group (one 16B hi write + one 16B lo write).
// K is fixed at 1024 columns.
// ---------------------------------------------------------------------------
__global__ __launch_bounds__(256)
void split_pack_kernel(const float* __restrict__ src,
                       __half* __restrict__ hi, __half* __restrict__ lo)
{
    uint32_t i = blockIdx.x * 256 + threadIdx.x;   // group index
    uint32_t row = i >> 7;
    uint32_t k = (i & 127u) * 8u;
    const float4* s = reinterpret_cast<const float4*>(src + ((size_t)row << 10) + k);
    float4 a = s[0], b = s[1];
    float f[8] = {a.x, a.y, a.z, a.w, b.x, b.y, b.z, b.w};
    uint32_t hw[4], lw[4];
    #pragma unroll
    for (int j = 0; j < 4; j++) {
        __half h0 = __float2half_rn(f[2 * j + 0]);
        __half h1 = __float2half_rn(f[2 * j + 1]);
        __half l0 = __float2half_rn((f[2 * j + 0] - __half2float(h0)) * LO_SCALE);
        __half l1 = __float2half_rn((f[2 * j + 1] - __half2float(h1)) * LO_SCALE);
        unsigned short uh0 = *reinterpret_cast<unsigned short*>(&h0);
        unsigned short uh1 = *reinterpret_cast<unsigned short*>(&h1);
        unsigned short ul0 = *reinterpret_cast<unsigned short*>(&l0);
        unsigned short ul1 = *reinterpret_cast<unsigned short*>(&l1);
        hw[j] = (uint32_t)uh0 | ((uint32_t)uh1 << 16);
        lw[j] = (uint32_t)ul0 | ((uint32_t)ul1 << 16);
    }
    uint32_t off = pack_off16(row, k);
    *reinterpret_cast<uint4*>(reinterpret_cast<char*>(hi) + off) =
        make_uint4(hw[0], hw[1], hw[2], hw[3]);
    *reinterpret_cast<uint4*>(reinterpret_cast<char*>(lo) + off) =
        make_uint4(lw[0], lw[1], lw[2], lw[3]);
}

// ---------------------------------------------------------------------------
// Split-precision GEMM on packed-tile operands:
//   C[m,n] = sum_k A[m,k]*B[n,k]
// hi*hi -> acc1 ; (lo'*hi + hi*lo') -> acc2 ; C = acc1 + acc2/4096.
// Tile 128x128, BK=64, 8 warps (2x4, warp tile 64x32). 3-stage pipeline
// fed by cp.async.bulk (one issuing thread) + mbarrier complete_tx.
// Output: fp32 (+bias) to fout, or packed fp16 split to hi_out/lo_out.
// ---------------------------------------------------------------------------
static constexpr uint32_t AHI_OFF = 0u;
static constexpr uint32_t ALO_OFF = 16384u;
static constexpr uint32_t BHI_OFF = 32768u;
static constexpr uint32_t BLO_OFF = 49152u;
static constexpr uint32_t STAGE   = 65536u;
static constexpr uint32_t SMEM_SZ = 1024u + 3u * STAGE;
static constexpr int NCH = 16;                 // K=1024 / 64

__global__ __launch_bounds__(256, 1)
void hmma_gemm(const __half* __restrict__ Ahi, const __half* __restrict__ Alo,
               const __half* __restrict__ Bhi, const __half* __restrict__ Blo,
               const float* __restrict__ bias, float* __restrict__ fout,
               __half* __restrict__ hi_out, __half* __restrict__ lo_out)
{
    extern __shared__ __align__(1024) char smem[];
    const uint32_t sbase = smem_u32(smem);
    const int tid = threadIdx.x;
    const int wid = tid >> 5;
    const int lane = tid & 31;
    const int wm = (wid >> 2) * 64;       // 2 warp rows
    const int wn = (wid & 3) * 32;        // 4 warp cols
    const int m0 = blockIdx.y << 7;       // BM = 128
    const int n0 = blockIdx.x << 7;       // BN = 128

    float acc1[4][4][4], acc2[4][4][4];
    #pragma unroll
    for (int i = 0; i < 4; i++)
        #pragma unroll
        for (int j = 0; j < 4; j++)
            #pragma unroll
            for (int r = 0; r < 4; r++) { acc1[i][j][r] = 0.0f; acc2[i][j][r] = 0.0f; }

    // mbarriers at sbase+0,8,16 ; stages at sbase+1024
    if (tid == 0) {
        mbar_init(sbase + 0, 1);
        mbar_init(sbase + 8, 1);
        mbar_init(sbase + 16, 1);
    }
    __syncthreads();

    auto issue = [&](int c, int s) {
        const uint32_t st  = sbase + 1024u + (uint32_t)s * STAGE;
        const uint32_t bar = sbase + (uint32_t)s * 8u;
        mbar_expect_tx(bar, STAGE);
        const size_t atile = ((size_t)(blockIdx.y * 16 + c)) << 14;
        const size_t btile = ((size_t)(blockIdx.x * 16 + c)) << 14;
        bulk_g2s(st + AHI_OFF, reinterpret_cast<const char*>(Ahi) + atile, 16384u, bar);
        bulk_g2s(st + ALO_OFF, reinterpret_cast<const char*>(Alo) + atile, 16384u, bar);
        bulk_g2s(st + BHI_OFF, reinterpret_cast<const char*>(Bhi) + btile, 16384u, bar);
        bulk_g2s(st + BLO_OFF, reinterpret_cast<const char*>(Blo) + btile, 16384u, bar);
    };

    if (tid == 0) { issue(0, 0); issue(1, 1); }

    #pragma unroll 1
    for (int c = 0; c < NCH; c++) {
        __syncthreads();                        // stage (c+2)%3 fully consumed
        if (tid == 0 && c + 2 < NCH) issue(c + 2, (c + 2) % 3);
        mbar_wait(sbase + (uint32_t)(c % 3) * 8u, (uint32_t)((c / 3) & 1));

        const uint32_t st = sbase + 1024u + (uint32_t)(c % 3) * STAGE;
        #pragma unroll
        for (int ks = 0; ks < 4; ks++) {
            uint32_t ah[4][4], al[4][4], bh[4][2], bl[4][2];
            #pragma unroll
            for (int i = 0; i < 4; i++) {
                int row = wm + i * 16 + (lane & 15);
                int ch = 2 * ks + (lane >> 4);
                uint32_t off = (uint32_t)(row * 128) +
                               (uint32_t)(((ch ^ (row & 7)) << 4));
                ldsm_x4(ah[i], st + AHI_OFF + off);
                ldsm_x4(al[i], st + ALO_OFF + off);
            }
            #pragma unroll
            for (int jj = 0; jj < 2; jj++) {
                int row = wn + jj * 16 + ((lane >> 4) << 3) + (lane & 7);
                int ch = 2 * ks + ((lane >> 3) & 1);
                uint32_t off = (uint32_t)(row * 128) +
                               (uint32_t)(((ch ^ (row & 7)) << 4));
                uint32_t t[4];
                ldsm_x4(t, st + BHI_OFF + off);
                bh[2 * jj][0] = t[0]; bh[2 * jj][1] = t[1];
                bh[2 * jj + 1][0] = t[2]; bh[2 * jj + 1][1] = t[3];
                ldsm_x4(t, st + BLO_OFF + off);
                bl[2 * jj][0] = t[0]; bl[2 * jj][1] = t[1];
                bl[2 * jj + 1][0] = t[2]; bl[2 * jj + 1][1] = t[3];
            }
            #pragma unroll
            for (int i = 0; i < 4; i++)
                #pragma unroll
                for (int j = 0; j < 4; j++) {
                    mma_f16(acc1[i][j], ah[i], bh[j]);
                    mma_f16(acc2[i][j], al[i], bh[j]);
                    mma_f16(acc2[i][j], ah[i], bl[j]);
                }
        }
    }
    __syncthreads();

    // Epilogue: combine -> padded smem [128][132] -> global
    float* stg = reinterpret_cast<float*>(smem + 1024);
    #pragma unroll
    for (int i = 0; i < 4; i++) {
        int row = wm + i * 16 + (lane >> 2);
        #pragma unroll
        for (int j = 0; j < 4; j++) {
            int col = wn + j * 8 + (lane & 3) * 2;
            stg[row * 132 + col]           = fmaf(acc2[i][j][0], LO_INV, acc1[i][j][0]);
            stg[row * 132 + col + 1]       = fmaf(acc2[i][j][1], LO_INV, acc1[i][j][1]);
            stg[(row + 8) * 132 + col]     = fmaf(acc2[i][j][2], LO_INV, acc1[i][j][2]);
            stg[(row + 8) * 132 + col + 1] = fmaf(acc2[i][j][3], LO_INV, acc1[i][j][3]);
        }
    }
    __syncthreads();

    if (hi_out == nullptr) {
        #pragma unroll
        for (int it = 0; it < 16; it++) {
            int idx = it * 256 + tid;        // 4096 float4 slots
            int r = idx >> 5;
            int c4 = (idx & 31) << 2;
            float4 v = *reinterpret_cast<const float4*>(&stg[r * 132 + c4]);
            if (bias != nullptr) {
                const float4 b = *reinterpret_cast<const float4*>(&bias[n0 + c4]);
                v.x += b.x; v.y += b.y; v.z += b.z; v.w += b.w;
            }
            *reinterpret_cast<float4*>(&fout[(size_t)(m0 + r) * 1024 + n0 + c4]) = v;
        }
    } else {
        // Split-write C into packed-tile fp16 hi/lo (rows = m, k = n).
        #pragma unroll
        for (int it = 0; it < 8; it++) {
            int g = it * 256 + tid;          // 2048 8-elem groups
            int r = g >> 4;
            int c8 = (g & 15) << 3;
            float4 va = *reinterpret_cast<const float4*>(&stg[r * 132 + c8]);
            float4 vb = *reinterpret_cast<const float4*>(&stg[r * 132 + c8 + 4]);
            float f[8] = {va.x, va.y, va.z, va.w, vb.x, vb.y, vb.z, vb.w};
            uint32_t hw[4], lw[4];
            #pragma unroll
            for (int j = 0; j < 4; j++) {
                __half h0 = __float2half_rn(f[2 * j + 0]);
                __half h1 = __float2half_rn(f[2 * j + 1]);
                __half l0 = __float2half_rn((f[2 * j + 0] - __half2float(h0)) * LO_SCALE);
                __half l1 = __float2half_rn((f[2 * j + 1] - __half2float(h1)) * LO_SCALE);
                unsigned short uh0 = *reinterpret_cast<unsigned short*>(&h0);
                unsigned short uh1 = *reinterpret_cast<unsigned short*>(&h1);
                unsigned short ul0 = *reinterpret_cast<unsigned short*>(&l0);
                unsigned short ul1 = *reinterpret_cast<unsigned short*>(&l1);
                hw[j] = (uint32_t)uh0 | ((uint32_t)uh1 << 16);
                lw[j] = (uint32_t)ul0 | ((uint32_t)ul1 << 16);
            }
            uint32_t off = pack_off16((uint32_t)(m0 + r), (uint32_t)(n0 + c8));
            *reinterpret_cast<uint4*>(reinterpret_cast<char*>(hi_out) + off) =
                make_uint4(hw[0], hw[1], hw[2], hw[3]);
            *reinterpret_cast<uint4*>(reinterpret_cast<char*>(lo_out) + off) =
                make_uint4(lw[0], lw[1], lw[2], lw[3]);
        }
    }
}

// ---------------------------------------------------------------------------
// LIF scan over T (soft reset) + time-mean pooling. float4 per thread,
// 16-deep prefetch; 128 blocks x 64 threads.
// ---------------------------------------------------------------------------
__global__ __launch_bounds__(64)
void lif_kernel(const float* __restrict__ h2, float* __restrict__ pooled)
{
    int idx = blockIdx.x * 64 + threadIdx.x;   // 0..8191
    int b = idx >> 8;
    int g4 = idx & 255;
    const float4* p = reinterpret_cast<const float4*>(h2 + ((size_t)b << 20)) + g4;

    float v[4] = {0, 0, 0, 0}, acc[4] = {0, 0, 0, 0};
    for (int t0 = 0; t0 < 1024; t0 += 16) {
        float4 xv[16];
        #pragma unroll
        for (int i = 0; i < 16; i++)
            xv[i] = __ldg(p + (size_t)(t0 + i) * 256);
        #pragma unroll
        for (int i = 0; i < 16; i++) {
            float xs[4] = {xv[i].x, xv[i].y, xv[i].z, xv[i].w};
            #pragma unroll
            for (int c = 0; c < 4; c++) {
                v[c] = __fadd_rn(v[c], __fmul_rn(__fsub_rn(xs[c], v[c]), 0.5f));
                if (v[c] >= 1.0f) { acc[c] += 1.0f; v[c] = __fsub_rn(v[c], 1.0f); }
            }
        }
    }
    float4 r;
    r.x = acc[0] * (1.0f / 1024.0f); r.y = acc[1] * (1.0f / 1024.0f);
    r.z = acc[2] * (1.0f / 1024.0f); r.w = acc[3] * (1.0f / 1024.0f);
    reinterpret_cast<float4*>(pooled)[idx] = r;
}

// ---------------------------------------------------------------------------
// out[b,o] = sum_g pooled[b,g] * W_out[o,g] + b_out[o]
// ---------------------------------------------------------------------------
__global__ __launch_bounds__(256)
void head_kernel(const float* __restrict__ pooled,
                 const float* __restrict__ W_out,
                 const float* __restrict__ b_out,
                 float* __restrict__ out)
{
    int b = blockIdx.x / 10;
    int o = blockIdx.x % 10;
    float s = 0.0f;
    for (int g = threadIdx.x; g < 1024; g += 256)
        s = fmaf(pooled[b * 1024 + g], W_out[o * 1024 + g], s);
    s = block_reduce_sum(s);
    if (threadIdx.x == 0) out[blockIdx.x] = s + b_out[o];
}

// ---------------------------------------------------------------------------
extern "C" void kernel_launch(void* const* d_in, const int* in_sizes, int n_in,
                              void* d_out, int out_size)
{
    (void)in_sizes; (void)n_in; (void)out_size;
    const float* x      = (const float*)d_in[0];
    const float* W_proj = (const float*)d_in[1];
    const float* b_proj = (const float*)d_in[2];
    const float* W_hid  = (const float*)d_in[3];
    const float* b_hid  = (const float*)d_in[4];
    const float* W_out  = (const float*)d_in[5];
    const float* b_out  = (const float*)d_in[6];
    float* out = (float*)d_out;

    float *wprojT, *bcomb, *h2, *pooled;
    __half *xhi, *xlo, *whi, *wlo, *ahi, *alo, *bthi, *btlo;
    cudaGetSymbolAddress((void**)&wprojT, g_wprojT);
    cudaGetSymbolAddress((void**)&bcomb,  g_bcomb);
    cudaGetSymbolAddress((void**)&h2,     g_h2);
    cudaGetSymbolAddress((void**)&pooled, g_pooled);
    cudaGetSymbolAddress((void**)&xhi,    g_xhi);
    cudaGetSymbolAddress((void**)&xlo,    g_xlo);
    cudaGetSymbolAddress((void**)&whi,    g_whi);
    cudaGetSymbolAddress((void**)&wlo,    g_wlo);
    cudaGetSymbolAddress((void**)&ahi,    g_ahi);
    cudaGetSymbolAddress((void**)&alo,    g_alo);
    cudaGetSymbolAddress((void**)&bthi,   g_bthi);
    cudaGetSymbolAddress((void**)&btlo,   g_btlo);

    cudaFuncSetAttribute(hmma_gemm, cudaFuncAttributeMaxDynamicSharedMemorySize,
                         (int)SMEM_SZ);

    // 0) x -> packed (xhi, xlo)
    split_pack_kernel<<<16384, 256>>>(x, xhi, xlo);
    // 1) W_projT = W_proj^T ; b_comb
    prep_kernel<<<2048, 256>>>(W_proj, W_hid, b_proj, b_hid, wprojT, bcomb);
    // 2,3) packed splits of W_hid and W_projT
    split_pack_kernel<<<512, 256>>>(W_hid,  ahi,  alo);
    split_pack_kernel<<<512, 256>>>(wprojT, bthi, btlo);
    // 4) W_comb = W_hid @ W_projT^T, split-written packed to (whi, wlo)
    hmma_gemm<<<dim3(8, 8), 256, SMEM_SZ>>>(
        ahi, alo, bthi, btlo, nullptr, nullptr, whi, wlo);
    // 5) h2 = x @ W_comb^T + b_comb
    hmma_gemm<<<dim3(8, 256), 256, SMEM_SZ>>>(
        xhi, xlo, whi, wlo, bcomb, h2, nullptr, nullptr);
    // 6) LIF + pool
    lif_kernel<<<128, 64>>>(h2, pooled);
    // 7) head
    head_kernel<<<320, 256>>>(pooled, W_out, b_out, out);
}

// round 9
// speedup vs baseline: 1.1253x; 1.0387x over previous
#include <cuda_runtime.h>
#include <cuda_fp16.h>
#include <cstdint>
#include <cstddef>

#define DINL __device__ __forceinline__

// ---------------------------------------------------------------------------
// Scratch (device globals; no allocation allowed)
// Packed layout for all fp16 GEMM operands: 16 KB tiles of (128 rows x 64 k),
// row-major over (rowtile, ktile), interior pre-swizzled for ldmatrix.
// ---------------------------------------------------------------------------
__device__ float g_wprojT[1024u * 1024u];
__device__ float g_bcomb[1024];
__device__ float g_h2[32u * 1024u * 1024u];     // [B*T, H] fp32 (134 MB)
__device__ float g_pooled[32 * 1024];
__device__ __align__(128) __half g_xhi[32u * 1024u * 1024u];
__device__ __align__(128) __half g_xlo[32u * 1024u * 1024u];
__device__ __align__(128) __half g_whi[1024u * 1024u];
__device__ __align__(128) __half g_wlo[1024u * 1024u];
__device__ __align__(128) __half g_ahi[1024u * 1024u];   // W_hid split
__device__ __align__(128) __half g_alo[1024u * 1024u];
__device__ __align__(128) __half g_bthi[1024u * 1024u];  // W_projT split
__device__ __align__(128) __half g_btlo[1024u * 1024u];

// Residual scale: lo' = (x - hi) * 2^12, combined as acc1 + acc2 * 2^-12.
static constexpr float LO_SCALE = 4096.0f;
static constexpr float LO_INV   = 1.0f / 4096.0f;

// ---------------------------------------------------------------------------
// PTX helpers (compute_103 baseline-safe)
// ---------------------------------------------------------------------------
DINL uint32_t smem_u32(const void* p) {
    uint32_t r;
    asm("{ .reg .u64 t; cvta.to.shared.u64 t, %1; cvt.u32.u64 %0, t; }"
        : "=r"(r) : "l"(p));
    return r;
}
DINL void ldsm_x4(uint32_t* r, uint32_t addr) {
    asm volatile("ldmatrix.sync.aligned.m8n8.x4.shared.b16 {%0,%1,%2,%3}, [%4];"
                 : "=r"(r[0]), "=r"(r[1]), "=r"(r[2]), "=r"(r[3]) : "r"(addr));
}
DINL void mma_f16(float* d, const uint32_t* a, const uint32_t* b) {
    asm volatile(
        "mma.sync.aligned.m16n8k16.row.col.f32.f16.f16.f32 "
        "{%0,%1,%2,%3}, {%4,%5,%6,%7}, {%8,%9}, {%0,%1,%2,%3};"
        : "+f"(d[0]), "+f"(d[1]), "+f"(d[2]), "+f"(d[3])
        : "r"(a[0]), "r"(a[1]), "r"(a[2]), "r"(a[3]), "r"(b[0]), "r"(b[1]));
}
DINL void mbar_init(uint32_t addr, uint32_t cnt) {
    asm volatile("mbarrier.init.shared.b64 [%0], %1;" :: "r"(addr), "r"(cnt) : "memory");
}
DINL void mbar_expect_tx(uint32_t addr, uint32_t bytes) {
    asm volatile("mbarrier.arrive.expect_tx.shared.b64 _, [%0], %1;"
                 :: "r"(addr), "r"(bytes) : "memory");
}
DINL void mbar_wait(uint32_t addr, uint32_t parity) {
    asm volatile(
        "{\n\t.reg .pred P;\n"
        "W1_%=:\n\tmbarrier.try_wait.parity.acquire.cta.shared::cta.b64 P, [%0], %1, 0x989680;\n\t"
        "@P bra W2_%=;\n\tbra W1_%=;\nW2_%=:\n\t}"
        :: "r"(addr), "r"(parity) : "memory");
}
// 1D bulk async copy global->smem, completion via mbarrier complete_tx.
DINL void bulk_g2s(uint32_t dst, const void* src, uint32_t bytes, uint32_t bar) {
    asm volatile(
        "cp.async.bulk.shared::cluster.global.mbarrier::complete_tx::bytes "
        "[%0], [%1], %2, [%3];"
        :: "r"(dst), "l"(src), "r"(bytes), "r"(bar) : "memory");
}

// Packed-tile byte offset of the 16B group holding (row, k..k+7).
DINL uint32_t pack_off16(uint32_t row, uint32_t k) {
    uint32_t tile  = (row >> 7) * 16u + (k >> 6);
    uint32_t local = (row & 127u) * 128u + ((k >> 3) & 7u) * 16u;
    local ^= (local >> 3) & 0x70u;           // SW128 swizzle
    return tile * 16384u + local;
}

// ---------------------------------------------------------------------------
// Block reduction helper (256 threads)
// ---------------------------------------------------------------------------
DINL float block_reduce_sum(float v) {
    __shared__ float sh[8];
    int lane = threadIdx.x & 31;
    int w = threadIdx.x >> 5;
    #pragma unroll
    for (int o = 16; o > 0; o >>= 1) v += __shfl_down_sync(0xFFFFFFFFu, v, o);
    if (lane == 0) sh[w] = v;
    __syncthreads();
    if (w == 0) {
        v = (lane < 8) ? sh[lane] : 0.0f;
        #pragma unroll
        for (int o = 4; o > 0; o >>= 1) v += __shfl_down_sync(0xFFFFFFFFu, v, o);
    }
    return v;
}

// ---------------------------------------------------------------------------
// Prep kernel: blocks [0,1024) transpose W_proj -> W_projT (32x32 tiles);
// blocks [1024,2048) compute b_comb[g] = W_hid[g,:]@b_proj + b_hid[g].
// ---------------------------------------------------------------------------
__global__ __launch_bounds__(256)
void prep_kernel(const float* __restrict__ W_proj,
                 const float* __restrict__ W_hid,
                 const float* __restrict__ b_proj,
                 const float* __restrict__ b_hid,
                 float* __restrict__ wprojT,
                 float* __restrict__ bcomb)
{
    if (blockIdx.x < 1024) {
        __shared__ float tile[32][33];
        int bx = blockIdx.x & 31, by = blockIdx.x >> 5;
        int tx = threadIdx.x & 31, ty = threadIdx.x >> 5;  // ty 0..7
        int x = bx * 32 + tx;
        #pragma unroll
        for (int j = 0; j < 32; j += 8)
            tile[ty + j][tx] = W_proj[(size_t)(by * 32 + ty + j) * 1024 + x];
        __syncthreads();
        x = by * 32 + tx;
        #pragma unroll
        for (int j = 0; j < 32; j += 8)
            wprojT[(size_t)(bx * 32 + ty + j) * 1024 + x] = tile[tx][ty + j];
    } else {
        int g = blockIdx.x - 1024;
        float s = 0.0f;
        for (int h = threadIdx.x; h < 1024; h += 256)
            s = fmaf(W_hid[g * 1024 + h], b_proj[h], s);
        s = block_reduce_sum(s);
        if (threadIdx.x == 0) bcomb[g] = s + b_hid[g];
    }
}

// ---------------------------------------------------------------------------
// fp32 row-major -> packed-swizzled-tile (fp16 hi, fp16 lo*4096).
// ---------------------------------------------------------------------------
__global__ __launch_bounds__(256)
void split_pack_kernel(const float* __restrict__ src,
                       __half* __restrict__ hi, __half* __restrict__ lo)
{
    uint32_t i = blockIdx.x * 256 + threadIdx.x;   // group index
    uint32_t row = i >> 7;
    uint32_t k = (i & 127u) * 8u;
    const float4* s = reinterpret_cast<const float4*>(src + ((size_t)row << 10) + k);
    float4 a = s[0], b = s[1];
    float f[8] = {a.x, a.y, a.z, a.w, b.x, b.y, b.z, b.w};
    uint32_t hw[4], lw[4];
    #pragma unroll
    for (int j = 0; j < 4; j++) {
        __half h0 = __float2half_rn(f[2 * j + 0]);
        __half h1 = __float2half_rn(f[2 * j + 1]);
        __half l0 = __float2half_rn((f[2 * j + 0] - __half2float(h0)) * LO_SCALE);
        __half l1 = __float2half_rn((f[2 * j + 1] - __half2float(h1)) * LO_SCALE);
        unsigned short uh0 = *reinterpret_cast<unsigned short*>(&h0);
        unsigned short uh1 = *reinterpret_cast<unsigned short*>(&h1);
        unsigned short ul0 = *reinterpret_cast<unsigned short*>(&l0);
        unsigned short ul1 = *reinterpret_cast<unsigned short*>(&l1);
        hw[j] = (uint32_t)uh0 | ((uint32_t)uh1 << 16);
        lw[j] = (uint32_t)ul0 | ((uint32_t)ul1 << 16);
    }
    uint32_t off = pack_off16(row, k);
    *reinterpret_cast<uint4*>(reinterpret_cast<char*>(hi) + off) =
        make_uint4(hw[0], hw[1], hw[2], hw[3]);
    *reinterpret_cast<uint4*>(reinterpret_cast<char*>(lo) + off) =
        make_uint4(lw[0], lw[1], lw[2], lw[3]);
}

// ---------------------------------------------------------------------------
// Shared GEMM constants
// ---------------------------------------------------------------------------
static constexpr uint32_t AHI_OFF = 0u;
static constexpr uint32_t ALO_OFF = 16384u;
static constexpr uint32_t BHI_OFF = 32768u;
static constexpr uint32_t BLO_OFF = 49152u;
static constexpr uint32_t STAGE   = 65536u;
static constexpr uint32_t SMEM_SZ = 1024u + 3u * STAGE;
static constexpr int NCH = 16;                 // K=1024 / 64

// ---------------------------------------------------------------------------
// Small (non-persistent) split-precision GEMM for W_comb (64 tiles).
// Writes packed fp16 split output.
// ---------------------------------------------------------------------------
__global__ __launch_bounds__(256, 1)
void hmma_gemm_small(const __half* __restrict__ Ahi, const __half* __restrict__ Alo,
                     const __half* __restrict__ Bhi, const __half* __restrict__ Blo,
                     __half* __restrict__ hi_out, __half* __restrict__ lo_out)
{
    extern __shared__ __align__(1024) char smem[];
    const uint32_t sbase = smem_u32(smem);
    const int tid = threadIdx.x;
    const int wid = tid >> 5;
    const int lane = tid & 31;
    const int wm = (wid >> 2) * 64;
    const int wn = (wid & 3) * 32;
    const int m0 = blockIdx.y << 7;
    const int n0 = blockIdx.x << 7;

    float acc1[4][4][4], acc2[4][4][4];
    #pragma unroll
    for (int i = 0; i < 4; i++)
        #pragma unroll
        for (int j = 0; j < 4; j++)
            #pragma unroll
            for (int r = 0; r < 4; r++) { acc1[i][j][r] = 0.0f; acc2[i][j][r] = 0.0f; }

    if (tid == 0) {
        mbar_init(sbase + 0, 1);
        mbar_init(sbase + 8, 1);
        mbar_init(sbase + 16, 1);
    }
    __syncthreads();

    auto issue = [&](int c, int s) {
        const uint32_t st  = sbase + 1024u + (uint32_t)s * STAGE;
        const uint32_t bar = sbase + (uint32_t)s * 8u;
        mbar_expect_tx(bar, STAGE);
        const size_t atile = ((size_t)(blockIdx.y * 16 + c)) << 14;
        const size_t btile = ((size_t)(blockIdx.x * 16 + c)) << 14;
        bulk_g2s(st + AHI_OFF, reinterpret_cast<const char*>(Ahi) + atile, 16384u, bar);
        bulk_g2s(st + ALO_OFF, reinterpret_cast<const char*>(Alo) + atile, 16384u, bar);
        bulk_g2s(st + BHI_OFF, reinterpret_cast<const char*>(Bhi) + btile, 16384u, bar);
        bulk_g2s(st + BLO_OFF, reinterpret_cast<const char*>(Blo) + btile, 16384u, bar);
    };

    if (tid == 0) { issue(0, 0); issue(1, 1); }

    #pragma unroll 1
    for (int c = 0; c < NCH; c++) {
        __syncthreads();
        if (tid == 0 && c + 2 < NCH) issue(c + 2, (c + 2) % 3);
        mbar_wait(sbase + (uint32_t)(c % 3) * 8u, (uint32_t)((c / 3) & 1));

        const uint32_t st = sbase + 1024u + (uint32_t)(c % 3) * STAGE;
        #pragma unroll
        for (int ks = 0; ks < 4; ks++) {
            uint32_t ah[4][4], al[4][4], bh[4][2], bl[4][2];
            #pragma unroll
            for (int i = 0; i < 4; i++) {
                int row = wm + i * 16 + (lane & 15);
                int ch = 2 * ks + (lane >> 4);
                uint32_t off = (uint32_t)(row * 128) +
                               (uint32_t)(((ch ^ (row & 7)) << 4));
                ldsm_x4(ah[i], st + AHI_OFF + off);
                ldsm_x4(al[i], st + ALO_OFF + off);
            }
            #pragma unroll
            for (int jj = 0; jj < 2; jj++) {
                int row = wn + jj * 16 + ((lane >> 4) << 3) + (lane & 7);
                int ch = 2 * ks + ((lane >> 3) & 1);
                uint32_t off = (uint32_t)(row * 128) +
                               (uint32_t)(((ch ^ (row & 7)) << 4));
                uint32_t t[4];
                ldsm_x4(t, st + BHI_OFF + off);
                bh[2 * jj][0] = t[0]; bh[2 * jj][1] = t[1];
                bh[2 * jj + 1][0] = t[2]; bh[2 * jj + 1][1] = t[3];
                ldsm_x4(t, st + BLO_OFF + off);
                bl[2 * jj][0] = t[0]; bl[2 * jj][1] = t[1];
                bl[2 * jj + 1][0] = t[2]; bl[2 * jj + 1][1] = t[3];
            }
            #pragma unroll
            for (int i = 0; i < 4; i++)
                #pragma unroll
                for (int j = 0; j < 4; j++) {
                    mma_f16(acc1[i][j], ah[i], bh[j]);
                    mma_f16(acc2[i][j], al[i], bh[j]);
                    mma_f16(acc2[i][j], ah[i], bl[j]);
                }
        }
    }
    __syncthreads();

    // Epilogue: combine -> padded smem -> packed fp16 split output
    float* stg = reinterpret_cast<float*>(smem + 1024);
    #pragma unroll
    for (int i = 0; i < 4; i++) {
        int row = wm + i * 16 + (lane >> 2);
        #pragma unroll
        for (int j = 0; j < 4; j++) {
            int col = wn + j * 8 + (lane & 3) * 2;
            stg[row * 132 + col]           = fmaf(acc2[i][j][0], LO_INV, acc1[i][j][0]);
            stg[row * 132 + col + 1]       = fmaf(acc2[i][j][1], LO_INV, acc1[i][j][1]);
            stg[(row + 8) * 132 + col]     = fmaf(acc2[i][j][2], LO_INV, acc1[i][j][2]);
            stg[(row + 8) * 132 + col + 1] = fmaf(acc2[i][j][3], LO_INV, acc1[i][j][3]);
        }
    }
    __syncthreads();

    #pragma unroll
    for (int it = 0; it < 8; it++) {
        int g = it * 256 + tid;          // 2048 8-elem groups
        int r = g >> 4;
        int c8 = (g & 15) << 3;
        float4 va = *reinterpret_cast<const float4*>(&stg[r * 132 + c8]);
        float4 vb = *reinterpret_cast<const float4*>(&stg[r * 132 + c8 + 4]);
        float f[8] = {va.x, va.y, va.z, va.w, vb.x, vb.y, vb.z, vb.w};
        uint32_t hw[4], lw[4];
        #pragma unroll
        for (int j = 0; j < 4; j++) {
            __half h0 = __float2half_rn(f[2 * j + 0]);
            __half h1 = __float2half_rn(f[2 * j + 1]);
            __half l0 = __float2half_rn((f[2 * j + 0] - __half2float(h0)) * LO_SCALE);
            __half l1 = __float2half_rn((f[2 * j + 1] - __half2float(h1)) * LO_SCALE);
            unsigned short uh0 = *reinterpret_cast<unsigned short*>(&h0);
            unsigned short uh1 = *reinterpret_cast<unsigned short*>(&h1);
            unsigned short ul0 = *reinterpret_cast<unsigned short*>(&l0);
            unsigned short ul1 = *reinterpret_cast<unsigned short*>(&l1);
            hw[j] = (uint32_t)uh0 | ((uint32_t)uh1 << 16);
            lw[j] = (uint32_t)ul0 | ((uint32_t)ul1 << 16);
        }
        uint32_t off = pack_off16((uint32_t)(m0 + r), (uint32_t)(n0 + c8));
        *reinterpret_cast<uint4*>(reinterpret_cast<char*>(hi_out) + off) =
            make_uint4(hw[0], hw[1], hw[2], hw[3]);
        *reinterpret_cast<uint4*>(reinterpret_cast<char*>(lo_out) + off) =
            make_uint4(lw[0], lw[1], lw[2], lw[3]);
    }
}

// ---------------------------------------------------------------------------
// PERSISTENT main GEMM: h2 = x @ Wcomb^T + bias.  148 CTAs loop over the
// 2048 (16 n x 256 m) tiles; the 3-stage bulk-copy ring never drains across
// tile boundaries. Epilogue writes float2 fragments directly to gmem.
// ---------------------------------------------------------------------------
static constexpr int PGRID = 148;
static constexpr int NTILES = 2048;            // (256 m-tiles) x (8 n-tiles)

__global__ __launch_bounds__(256, 1)
void hmma_gemm_persistent(const __half* __restrict__ Ahi,
                          const __half* __restrict__ Alo,
                          const __half* __restrict__ Bhi,
                          const __half* __restrict__ Blo,
                          const float* __restrict__ bias,
                          float* __restrict__ fout)
{
    extern __shared__ __align__(1024) char smem[];
    const uint32_t sbase = smem_u32(smem);
    const int tid = threadIdx.x;
    const int wid = tid >> 5;
    const int lane = tid & 31;
    const int wm = (wid >> 2) * 64;
    const int wn = (wid & 3) * 32;

    int ntile = 0;
    for (int t = blockIdx.x; t < NTILES; t += PGRID) ntile++;
    const int G = ntile * NCH;                 // total chunks for this CTA

    if (tid == 0) {
        mbar_init(sbase + 0, 1);
        mbar_init(sbase + 8, 1);
        mbar_init(sbase + 16, 1);
    }
    __syncthreads();

    auto issue = [&](int g) {
        const int s = g % 3;
        const uint32_t st  = sbase + 1024u + (uint32_t)s * STAGE;
        const uint32_t bar = sbase + (uint32_t)s * 8u;
        const int tile = blockIdx.x + (g >> 4) * PGRID;
        const int c = g & 15;
        mbar_expect_tx(bar, STAGE);
        const size_t atile = ((size_t)((tile >> 3) * 16 + c)) << 14;  // m-tile
        const size_t btile = ((size_t)((tile & 7) * 16 + c)) << 14;   // n-tile
        bulk_g2s(st + AHI_OFF, reinterpret_cast<const char*>(Ahi) + atile, 16384u, bar);
        bulk_g2s(st + ALO_OFF, reinterpret_cast<const char*>(Alo) + atile, 16384u, bar);
        bulk_g2s(st + BHI_OFF, reinterpret_cast<const char*>(Bhi) + btile, 16384u, bar);
        bulk_g2s(st + BLO_OFF, reinterpret_cast<const char*>(Blo) + btile, 16384u, bar);
    };

    float acc1[4][4][4], acc2[4][4][4];
    #pragma unroll
    for (int i = 0; i < 4; i++)
        #pragma unroll
        for (int j = 0; j < 4; j++)
            #pragma unroll
            for (int r = 0; r < 4; r++) { acc1[i][j][r] = 0.0f; acc2[i][j][r] = 0.0f; }

    if (tid == 0) { issue(0); if (G > 1) issue(1); }

    #pragma unroll 1
    for (int g = 0; g < G; g++) {
        __syncthreads();                        // stage (g+2)%3 fully consumed
        if (tid == 0 && g + 2 < G) issue(g + 2);
        mbar_wait(sbase + (uint32_t)(g % 3) * 8u, (uint32_t)((g / 3) & 1));

        const uint32_t st = sbase + 1024u + (uint32_t)(g % 3) * STAGE;
        #pragma unroll
        for (int ks = 0; ks < 4; ks++) {
            uint32_t ah[4][4], al[4][4], bh[4][2], bl[4][2];
            #pragma unroll
            for (int i = 0; i < 4; i++) {
                int row = wm + i * 16 + (lane & 15);
                int ch = 2 * ks + (lane >> 4);
                uint32_t off = (uint32_t)(row * 128) +
                               (uint32_t)(((ch ^ (row & 7)) << 4));
                ldsm_x4(ah[i], st + AHI_OFF + off);
                ldsm_x4(al[i], st + ALO_OFF + off);
            }
            #pragma unroll
            for (int jj = 0; jj < 2; jj++) {
                int row = wn + jj * 16 + ((lane >> 4) << 3) + (lane & 7);
                int ch = 2 * ks + ((lane >> 3) & 1);
                uint32_t off = (uint32_t)(row * 128) +
                               (uint32_t)(((ch ^ (row & 7)) << 4));
                uint32_t t[4];
                ldsm_x4(t, st + BHI_OFF + off);
                bh[2 * jj][0] = t[0]; bh[2 * jj][1] = t[1];
                bh[2 * jj + 1][0] = t[2]; bh[2 * jj + 1][1] = t[3];
                ldsm_x4(t, st + BLO_OFF + off);
                bl[2 * jj][0] = t[0]; bl[2 * jj][1] = t[1];
                bl[2 * jj + 1][0] = t[2]; bl[2 * jj + 1][1] = t[3];
            }
            #pragma unroll
            for (int i = 0; i < 4; i++)
                #pragma unroll
                for (int j = 0; j < 4; j++) {
                    mma_f16(acc1[i][j], ah[i], bh[j]);
                    mma_f16(acc2[i][j], al[i], bh[j]);
                    mma_f16(acc2[i][j], ah[i], bl[j]);
                }
        }

        if ((g & 15) == 15) {
            // Tile complete: direct register epilogue (no smem staging).
            const int tile = blockIdx.x + (g >> 4) * PGRID;
            const int m0 = (tile >> 3) << 7;
            const int n0 = (tile & 7) << 7;
            #pragma unroll
            for (int i = 0; i < 4; i++) {
                int row = m0 + wm + i * 16 + (lane >> 2);
                #pragma unroll
                for (int j = 0; j < 4; j++) {
                    int col = n0 + wn + j * 8 + (lane & 3) * 2;
                    float b0 = __ldg(bias + col);
                    float b1 = __ldg(bias + col + 1);
                    float2 v0, v1;
                    v0.x = fmaf(acc2[i][j][0], LO_INV, acc1[i][j][0]) + b0;
                    v0.y = fmaf(acc2[i][j][1], LO_INV, acc1[i][j][1]) + b1;
                    v1.x = fmaf(acc2[i][j][2], LO_INV, acc1[i][j][2]) + b0;
                    v1.y = fmaf(acc2[i][j][3], LO_INV, acc1[i][j][3]) + b1;
                    *reinterpret_cast<float2*>(&fout[(size_t)row * 1024 + col]) = v0;
                    *reinterpret_cast<float2*>(&fout[(size_t)(row + 8) * 1024 + col]) = v1;
                    acc1[i][j][0] = 0.0f; acc1[i][j][1] = 0.0f;
                    acc1[i][j][2] = 0.0f; acc1[i][j][3] = 0.0f;
                    acc2[i][j][0] = 0.0f; acc2[i][j][1] = 0.0f;
                    acc2[i][j][2] = 0.0f; acc2[i][j][3] = 0.0f;
                }
            }
        }
    }
}

// ---------------------------------------------------------------------------
// LIF scan over T (soft reset) + time-mean pooling. float4 per thread,
// 16-deep prefetch; 128 blocks x 64 threads.
// ---------------------------------------------------------------------------
__global__ __launch_bounds__(64)
void lif_kernel(const float* __restrict__ h2, float* __restrict__ pooled)
{
    int idx = blockIdx.x * 64 + threadIdx.x;   // 0..8191
    int b = idx >> 8;
    int g4 = idx & 255;
    const float4* p = reinterpret_cast<const float4*>(h2 + ((size_t)b << 20)) + g4;

    float v[4] = {0, 0, 0, 0}, acc[4] = {0, 0, 0, 0};
    for (int t0 = 0; t0 < 1024; t0 += 16) {
        float4 xv[16];
        #pragma unroll
        for (int i = 0; i < 16; i++)
            xv[i] = __ldg(p + (size_t)(t0 + i) * 256);
        #pragma unroll
        for (int i = 0; i < 16; i++) {
            float xs[4] = {xv[i].x, xv[i].y, xv[i].z, xv[i].w};
            #pragma unroll
            for (int c = 0; c < 4; c++) {
                v[c] = __fadd_rn(v[c], __fmul_rn(__fsub_rn(xs[c], v[c]), 0.5f));
                if (v[c] >= 1.0f) { acc[c] += 1.0f; v[c] = __fsub_rn(v[c], 1.0f); }
            }
        }
    }
    float4 r;
    r.x = acc[0] * (1.0f / 1024.0f); r.y = acc[1] * (1.0f / 1024.0f);
    r.z = acc[2] * (1.0f / 1024.0f); r.w = acc[3] * (1.0f / 1024.0f);
    reinterpret_cast<float4*>(pooled)[idx] = r;
}

// ---------------------------------------------------------------------------
// out[b,o] = sum_g pooled[b,g] * W_out[o,g] + b_out[o]
// ---------------------------------------------------------------------------
__global__ __launch_bounds__(256)
void head_kernel(const float* __restrict__ pooled,
                 const float* __restrict__ W_out,
                 const float* __restrict__ b_out,
                 float* __restrict__ out)
{
    int b = blockIdx.x / 10;
    int o = blockIdx.x % 10;
    float s = 0.0f;
    for (int g = threadIdx.x; g < 1024; g += 256)
        s = fmaf(pooled[b * 1024 + g], W_out[o * 1024 + g], s);
    s = block_reduce_sum(s);
    if (threadIdx.x == 0) out[blockIdx.x] = s + b_out[o];
}

// ---------------------------------------------------------------------------
extern "C" void kernel_launch(void* const* d_in, const int* in_sizes, int n_in,
                              void* d_out, int out_size)
{
    (void)in_sizes; (void)n_in; (void)out_size;
    const float* x      = (const float*)d_in[0];
    const float* W_proj = (const float*)d_in[1];
    const float* b_proj = (const float*)d_in[2];
    const float* W_hid  = (const float*)d_in[3];
    const float* b_hid  = (const float*)d_in[4];
    const float* W_out  = (const float*)d_in[5];
    const float* b_out  = (const float*)d_in[6];
    float* out = (float*)d_out;

    float *wprojT, *bcomb, *h2, *pooled;
    __half *xhi, *xlo, *whi, *wlo, *ahi, *alo, *bthi, *btlo;
    cudaGetSymbolAddress((void**)&wprojT, g_wprojT);
    cudaGetSymbolAddress((void**)&bcomb,  g_bcomb);
    cudaGetSymbolAddress((void**)&h2,     g_h2);
    cudaGetSymbolAddress((void**)&pooled, g_pooled);
    cudaGetSymbolAddress((void**)&xhi,    g_xhi);
    cudaGetSymbolAddress((void**)&xlo,    g_xlo);
    cudaGetSymbolAddress((void**)&whi,    g_whi);
    cudaGetSymbolAddress((void**)&wlo,    g_wlo);
    cudaGetSymbolAddress((void**)&ahi,    g_ahi);
    cudaGetSymbolAddress((void**)&alo,    g_alo);
    cudaGetSymbolAddress((void**)&bthi,   g_bthi);
    cudaGetSymbolAddress((void**)&btlo,   g_btlo);

    cudaFuncSetAttribute(hmma_gemm_small,
                         cudaFuncAttributeMaxDynamicSharedMemorySize, (int)SMEM_SZ);
    cudaFuncSetAttribute(hmma_gemm_persistent,
                         cudaFuncAttributeMaxDynamicSharedMemorySize, (int)SMEM_SZ);

    // 0) x -> packed (xhi, xlo)
    split_pack_kernel<<<16384, 256>>>(x, xhi, xlo);
    // 1) W_projT = W_proj^T ; b_comb
    prep_kernel<<<2048, 256>>>(W_proj, W_hid, b_proj, b_hid, wprojT, bcomb);
    // 2,3) packed splits of W_hid and W_projT
    split_pack_kernel<<<512, 256>>>(W_hid,  ahi,  alo);
    split_pack_kernel<<<512, 256>>>(wprojT, bthi, btlo);
    // 4) W_comb = W_hid @ W_projT^T, split-written packed to (whi, wlo)
    hmma_gemm_small<<<dim3(8, 8), 256, SMEM_SZ>>>(
        ahi, alo, bthi, btlo, whi, wlo);
    // 5) h2 = x @ W_comb^T + b_comb   (persistent, 148 CTAs)
    hmma_gemm_persistent<<<PGRID, 256, SMEM_SZ>>>(
        xhi, xlo, whi, wlo, bcomb, h2);
    // 6) LIF + pool
    lif_kernel<<<128, 64>>>(h2, pooled);
    // 7) head
    head_kernel<<<320, 256>>>(pooled, W_out, b_out, out);
}